// round 5
// baseline (speedup 1.0000x reference)
#include <cuda_runtime.h>
#include <math.h>

#define B_TOTAL 65536
#define NPAIR 8
typedef unsigned long long ull;

// Scratch: conv output activations (fc input), layout [B][256] float.
__device__ float g_flat[B_TOTAL * 256];

// ---- f32x2 helpers -------------------------------------------------------
__device__ __forceinline__ ull pack2(float a, float b) {
    ull r; asm("mov.b64 %0, {%1,%2};" : "=l"(r) : "f"(a), "f"(b)); return r;
}
__device__ __forceinline__ void unpk(ull v, float& a, float& b) {
    asm("mov.b64 {%0,%1}, %2;" : "=f"(a), "=f"(b) : "l"(v));
}
__device__ __forceinline__ void ffma2(ull& d, ull a, ull b) {
    asm("fma.rn.f32x2 %0, %1, %2, %0;" : "+l"(d) : "l"(a), "l"(b));
}

// stage one sample-pair (interleaved f32x2) into buf using threads
// tid0..tid0+nt-1 (caller guarantees tid in range)
__device__ __forceinline__ void stage_pair(ull* buf, const float* __restrict__ x,
                                           long b0, int tid, int nt) {
    const float4* A = (const float4*)(x + b0 * 784);
    const float4* C = (const float4*)(x + (b0 + 1) * 784);
    for (int i = tid; i < 196; i += nt) {
        float4 a4 = __ldg(&A[i]), c4 = __ldg(&C[i]);
        buf[4 * i + 0] = pack2(a4.x, c4.x);
        buf[4 * i + 1] = pack2(a4.y, c4.y);
        buf[4 * i + 2] = pack2(a4.z, c4.z);
        buf[4 * i + 3] = pack2(a4.w, c4.w);
    }
}

// ---------------------------------------------------------------------------
// Fused conv kernel. Block = 128 threads, loops over NPAIR sample-pairs.
// Double-buffered input staging: during phase-1 (threads 0..95 compute),
// threads 96..127 stage the next pair. 128 regs/thread (no spills).
// ---------------------------------------------------------------------------
__global__ void __launch_bounds__(128, 4) k_conv(const float* __restrict__ x,
                                                 const float* __restrict__ w1,
                                                 const float* __restrict__ b1,
                                                 const float* __restrict__ w2,
                                                 const float* __restrict__ b2) {
    __shared__ __align__(16) ull sx[2][784];
    __shared__ __align__(16) ull sp1[288];
    const int t = threadIdx.x;
    const long pair0 = (long)blockIdx.x * NPAIR;

    stage_pair(sx[0], x, pair0 * 2, t, 128);
    __syncthreads();

    for (int it = 0; it < NPAIR; it++) {
        const int cur = it & 1;
        const long b0 = (pair0 + it) * 2;

        // ---- phase 1 (t<96) + next-pair staging (t>=96) ----
        if (t < 96) {
            const int pxh = t & 3;
            const int py  = (t >> 2) % 12;
            const int co1 = t / 48;

            ull wd1[25];
#pragma unroll
            for (int i = 0; i < 25; i++) {
                float w = __ldg(&w1[co1 * 25 + i]);
                wd1[i] = pack2(w, w);
            }
            const float bias1 = __ldg(&b1[co1]);

            const ull* in = &sx[cur][(2 * py) * 28 + 6 * pxh];
            ull acc[2][6] = {{0,0,0,0,0,0},{0,0,0,0,0,0}};
#pragma unroll
            for (int iy = 0; iy < 6; iy++) {
                ull row[10];
#pragma unroll
                for (int c = 0; c < 10; c += 2) {
                    ulonglong2 v = *(const ulonglong2*)&in[iy * 28 + c];
                    row[c] = v.x; row[c + 1] = v.y;
                }
#pragma unroll
                for (int yy = 0; yy < 2; yy++) {
                    const int ky = iy - yy;
                    if (ky >= 0 && ky < 5) {
#pragma unroll
                        for (int cx = 0; cx < 6; cx++)
#pragma unroll
                            for (int kx = 0; kx < 5; kx++)
                                ffma2(acc[yy][cx], row[cx + kx], wd1[ky * 5 + kx]);
                    }
                }
            }
#pragma unroll
            for (int p = 0; p < 3; p++) {
                float a0,a1,e0,e1,c0,c1,d0,d1;
                unpk(acc[0][2*p],   a0,a1); unpk(acc[0][2*p+1], e0,e1);
                unpk(acc[1][2*p],   c0,c1); unpk(acc[1][2*p+1], d0,d1);
                float vA = fmaxf(fmaxf(fmaxf(a0,e0), fmaxf(c0,d0)) + bias1, 0.f);
                float vB = fmaxf(fmaxf(fmaxf(a1,e1), fmaxf(c1,d1)) + bias1, 0.f);
                sp1[co1 * 144 + py * 12 + pxh * 3 + p] = pack2(vA, vB);
            }
        } else if (it + 1 < NPAIR) {
            stage_pair(sx[cur ^ 1], x, b0 + 2, t - 96, 32);
        }
        __syncthreads();

        // ---- phase 2: conv2 + relu + pool, all 128 threads ----
        {
            const int pxh = t & 1;
            const int py  = (t >> 1) & 3;
            const int co  = t >> 3;
            const float bias2 = __ldg(&b2[co]);

            ull acc[2][4] = {{0,0,0,0},{0,0,0,0}};
#pragma unroll
            for (int ci = 0; ci < 2; ci++) {
                ull wd2[25];
#pragma unroll
                for (int i = 0; i < 25; i++) {
                    float w = __ldg(&w2[(co * 2 + ci) * 25 + i]);
                    wd2[i] = pack2(w, w);
                }
                const ull* in2 = &sp1[ci * 144 + (2 * py) * 12 + 4 * pxh];
#pragma unroll
                for (int iy = 0; iy < 6; iy++) {
                    ull row[8];
#pragma unroll
                    for (int c = 0; c < 8; c += 2) {
                        ulonglong2 v = *(const ulonglong2*)&in2[iy * 12 + c];
                        row[c] = v.x; row[c + 1] = v.y;
                    }
#pragma unroll
                    for (int yy = 0; yy < 2; yy++) {
                        const int ky = iy - yy;
                        if (ky >= 0 && ky < 5) {
#pragma unroll
                            for (int xx = 0; xx < 4; xx++)
#pragma unroll
                                for (int kx = 0; kx < 5; kx++)
                                    ffma2(acc[yy][xx], row[xx + kx], wd2[ky * 5 + kx]);
                        }
                    }
                }
            }

            float oA[2], oB[2];
#pragma unroll
            for (int p = 0; p < 2; p++) {
                float a0,a1,e0,e1,c0,c1,d0,d1;
                unpk(acc[0][2*p],   a0,a1); unpk(acc[0][2*p+1], e0,e1);
                unpk(acc[1][2*p],   c0,c1); unpk(acc[1][2*p+1], d0,d1);
                oA[p] = fmaxf(fmaxf(fmaxf(a0,e0), fmaxf(c0,d0)) + bias2, 0.f);
                oB[p] = fmaxf(fmaxf(fmaxf(a1,e1), fmaxf(c1,d1)) + bias2, 0.f);
            }
            const int off = co * 16 + py * 4 + pxh * 2;
            *(float2*)&g_flat[b0 * 256 + off]       = make_float2(oA[0], oA[1]);
            *(float2*)&g_flat[(b0 + 1) * 256 + off] = make_float2(oB[0], oB[1]);
        }
        __syncthreads();   // sp1 reuse + sx[nxt] ready for next iter
    }
}

// ---------------------------------------------------------------------------
// k_fc: fc1(256->64,relu) + fc2(64->2) + quantum + fc3 + log_softmax
// (unchanged from round 4 — conflict-free weight LDS.128, 4x8 lane tile)
// ---------------------------------------------------------------------------
__global__ void __launch_bounds__(256, 2) k_fc(const float* __restrict__ fc1w,
                                               const float* __restrict__ fc1b,
                                               const float* __restrict__ fc2w,
                                               const float* __restrict__ fc2b,
                                               const float* __restrict__ fc3w,
                                               const float* __restrict__ fc3b,
                                               const float* __restrict__ qp,
                                               float* __restrict__ out) {
    __shared__ __align__(16) ull s_w[64 * 130];

    const int tid  = threadIdx.x;
    const int warp = tid >> 5, lane = tid & 31;
    const int og = lane & 7, sg = lane >> 3;

    {
        const float2* wsrc = (const float2*)fc1w;
        for (int i = tid; i < 8192; i += 256) {
            float2 v = __ldg(&wsrc[i]);
            const int o = i >> 7, kk = i & 127;
            s_w[(kk >> 1) * 130 + 2 * o + (kk & 1)] = pack2(v.x, v.y);
        }
    }
    __syncthreads();

    const long wg = (long)blockIdx.x * 8 + warp;
    const long b0w = wg * 16;

    const ull* h0 = (const ull*)&g_flat[(b0w + sg * 4) * 256];
    const ull* wbase = &s_w[2 * og];

    ull acc[4][8];
#pragma unroll
    for (int j = 0; j < 4; j++)
#pragma unroll
        for (int oo = 0; oo < 8; oo++) acc[j][oo] = 0ULL;

#pragma unroll 2
    for (int kp = 0; kp < 64; kp++) {
        ull w0[8], w1[8];
#pragma unroll
        for (int oo = 0; oo < 8; oo++) {
            ulonglong2 v = *(const ulonglong2*)&wbase[kp * 130 + 16 * oo];
            w0[oo] = v.x; w1[oo] = v.y;
        }
        ull ha[4], hb[4];
#pragma unroll
        for (int j = 0; j < 4; j++) {
            ulonglong2 hv = __ldg((const ulonglong2*)&h0[j * 128 + 2 * kp]);
            ha[j] = hv.x; hb[j] = hv.y;
        }
#pragma unroll
        for (int j = 0; j < 4; j++)
#pragma unroll
            for (int oo = 0; oo < 8; oo++) {
                ffma2(acc[j][oo], ha[j], w0[oo]);
                ffma2(acc[j][oo], hb[j], w1[oo]);
            }
    }

    float p0[4] = {0,0,0,0}, p1[4] = {0,0,0,0};
#pragma unroll
    for (int oo = 0; oo < 8; oo++) {
        const int o = og + 8 * oo;
        const float bb  = __ldg(&fc1b[o]);
        const float w20 = __ldg(&fc2w[o]);
        const float w21 = __ldg(&fc2w[64 + o]);
#pragma unroll
        for (int j = 0; j < 4; j++) {
            float e, od; unpk(acc[j][oo], e, od);
            float v = fmaxf(e + od + bb, 0.f);
            p0[j] = fmaf(v, w20, p0[j]);
            p1[j] = fmaf(v, w21, p1[j]);
        }
    }
#pragma unroll
    for (int d = 1; d < 8; d <<= 1) {
#pragma unroll
        for (int j = 0; j < 4; j++) {
            p0[j] += __shfl_xor_sync(0xffffffffu, p0[j], d);
            p1[j] += __shfl_xor_sync(0xffffffffu, p1[j], d);
        }
    }
    float x0 = 0.f, x1 = 0.f;
#pragma unroll
    for (int j = 0; j < 4; j++)
        if (og == j) { x0 = p0[j]; x1 = p1[j]; }
    x0 += __ldg(&fc2b[0]);
    x1 += __ldg(&fc2b[1]);
    if (og >= 4) { x0 = 0.f; x1 = 0.f; }

    float cq[8], sq[8];
#pragma unroll
    for (int i = 0; i < 8; i++) {
        float p = __ldg(&qp[i]);
        sincosf(p, &sq[i], &cq[i]);
    }
    const float PI = 3.14159265358979323846f;
    const float ang = (PI - x0) * (PI - x1);
    const float P = x0 + x1, M = x0 - x1;
    float sPp, cPp, sPm, cPm, sMp, cMp, sMm, cMm;
    sincosf(P + ang, &sPp, &cPp);
    sincosf(P - ang, &sPm, &cPm);
    sincosf(M + ang, &sMp, &cMp);
    sincosf(M - ang, &sMm, &cMm);
    float r00 =  0.5f * cPp, i00 = -0.5f * sPp;
    float r01 =  0.5f * cMm, i01 = -0.5f * sMm;
    float r10 =  0.5f * cMp, i10 =  0.5f * sMp;
    float r11 =  0.5f * cPm, i11 =  0.5f * sPm;

#define ROT0(ii) { float c = cq[ii], s = sq[ii], a, bt;                      \
    a = r00; bt = r10; r00 = c*a - s*bt; r10 = s*a + c*bt;                   \
    a = i00; bt = i10; i00 = c*a - s*bt; i10 = s*a + c*bt;                   \
    a = r01; bt = r11; r01 = c*a - s*bt; r11 = s*a + c*bt;                   \
    a = i01; bt = i11; i01 = c*a - s*bt; i11 = s*a + c*bt; }
#define ROT1(ii) { float c = cq[ii], s = sq[ii], a, bt;                      \
    a = r00; bt = r01; r00 = c*a - s*bt; r01 = s*a + c*bt;                   \
    a = i00; bt = i01; i00 = c*a - s*bt; i01 = s*a + c*bt;                   \
    a = r10; bt = r11; r10 = c*a - s*bt; r11 = s*a + c*bt;                   \
    a = i10; bt = i11; i10 = c*a - s*bt; i11 = s*a + c*bt; }
#define CN01 { float tt; tt = r10; r10 = r11; r11 = tt; tt = i10; i10 = i11; i11 = tt; }
#define CN10 { float tt; tt = r01; r01 = r11; r11 = tt; tt = i01; i01 = i11; i11 = tt; }

    ROT0(0); ROT1(1); CN01;
    ROT0(2); ROT1(3); CN10;
    ROT0(4); ROT1(5); CN01;
    ROT0(6); ROT1(7);

    const float q = (r00 * r00 + i00 * i00) - (r01 * r01 + i01 * i01)
                  - (r10 * r10 + i10 * i10) + (r11 * r11 + i11 * i11);

    const float y  = fmaf(q, __ldg(&fc3w[0]), __ldg(&fc3b[0]));
    const float l0 = y, l1 = 1.0f - y;
    const float m  = fmaxf(l0, l1);
    const float lse = m + logf(expf(l0 - m) + expf(l1 - m));

    if (og < 4) {
        float2 res;
        res.x = l0 - lse;
        res.y = l1 - lse;
        ((float2*)out)[b0w + sg * 4 + og] = res;
    }
}

// ---------------------------------------------------------------------------
extern "C" void kernel_launch(void* const* d_in, const int* in_sizes, int n_in,
                              void* d_out, int out_size) {
    const float* x   = (const float*)d_in[0];
    const float* c1w = (const float*)d_in[1];
    const float* c1b = (const float*)d_in[2];
    const float* c2w = (const float*)d_in[3];
    const float* c2b = (const float*)d_in[4];
    const float* f1w = (const float*)d_in[5];
    const float* f1b = (const float*)d_in[6];
    const float* f2w = (const float*)d_in[7];
    const float* f2b = (const float*)d_in[8];
    const float* f3w = (const float*)d_in[9];
    const float* f3b = (const float*)d_in[10];
    const float* qp  = (const float*)d_in[11];
    float* out = (float*)d_out;

    k_conv<<<B_TOTAL / 2 / NPAIR, 128>>>(x, c1w, c1b, c2w, c2b);
    k_fc<<<B_TOTAL / 128, 256>>>(f1w, f1b, f2w, f2b, f3w, f3b, qp, out);
}

// round 6
// speedup vs baseline: 1.0567x; 1.0567x over previous
#include <cuda_runtime.h>
#include <math.h>

#define B_TOTAL 65536
#define NPAIR 16
typedef unsigned long long ull;

// Scratch: conv output activations (fc input), layout [B][256] float.
__device__ float g_flat[B_TOTAL * 256];

// ---- f32x2 helpers -------------------------------------------------------
__device__ __forceinline__ ull pack2(float a, float b) {
    ull r; asm("mov.b64 %0, {%1,%2};" : "=l"(r) : "f"(a), "f"(b)); return r;
}
__device__ __forceinline__ void unpk(ull v, float& a, float& b) {
    asm("mov.b64 {%0,%1}, %2;" : "=f"(a), "=f"(b) : "l"(v));
}
__device__ __forceinline__ void ffma2(ull& d, ull a, ull b) {
    asm("fma.rn.f32x2 %0, %1, %2, %0;" : "+l"(d) : "l"(a), "l"(b));
}
__device__ __forceinline__ ull add2(ull a, ull b) {
    ull r; asm("add.rn.f32x2 %0, %1, %2;" : "=l"(r) : "l"(a), "l"(b)); return r;
}

// sp1 padded layout: [ci][row 0..11][col 0..11], idx = ci*170 + row*14 + col
#define SP1_CI 170
#define SP1_ROW 14
#define SP1_SZ 340

__device__ __forceinline__ void stage_pair(ull* buf, const float* __restrict__ x,
                                           long b0, int tid, int nt) {
    const float4* A = (const float4*)(x + b0 * 784);
    const float4* C = (const float4*)(x + (b0 + 1) * 784);
    for (int i = tid; i < 196; i += nt) {
        float4 a4 = __ldg(&A[i]), c4 = __ldg(&C[i]);
        buf[4 * i + 0] = pack2(a4.x, c4.x);
        buf[4 * i + 1] = pack2(a4.y, c4.y);
        buf[4 * i + 2] = pack2(a4.z, c4.z);
        buf[4 * i + 3] = pack2(a4.w, c4.w);
    }
}

// ---------------------------------------------------------------------------
// Persistent warp-specialized conv kernel. Block = 256 threads:
//   warps 0-2 (t<96):   conv1+pool for pair it      (wd1 resident in regs)
//   warp 3  (96..127):  stage pair it+1
//   warps 4-7 (128..):  conv2+pool for pair it-1    (wd2 resident, ci split)
// One __syncthreads per iteration; sx/sp1 double-buffered.
// ---------------------------------------------------------------------------
__global__ void __launch_bounds__(256, 2) k_conv(const float* __restrict__ x,
                                                 const float* __restrict__ w1,
                                                 const float* __restrict__ b1,
                                                 const float* __restrict__ w2,
                                                 const float* __restrict__ b2) {
    __shared__ __align__(16) ull sx[2][784];
    __shared__ __align__(16) ull sp1[2][SP1_SZ];
    const int t = threadIdx.x;
    const long pair0 = (long)blockIdx.x * NPAIR;

    // ---- role-specific persistent state ----
    ull wreg[25];        // wd1 for phase1 threads, wd2(ci) for phase2 threads
    float bias = 0.f;
    int co1 = 0, py1 = 0, pxh1 = 0;          // phase1 coords
    int co2 = 0, ci2 = 0, py2 = 0;           // phase2 coords

    if (t < 96) {
        co1 = t / 48;
        const int rem = t % 48;
        py1 = rem >> 2; pxh1 = rem & 3;
#pragma unroll
        for (int i = 0; i < 25; i++) {
            float w = __ldg(&w1[co1 * 25 + i]);
            wreg[i] = pack2(w, w);
        }
        bias = __ldg(&b1[co1]);
    } else if (t >= 128) {
        const int u = t - 128;
        co2 = u >> 3; ci2 = (u >> 2) & 1; py2 = u & 3;
#pragma unroll
        for (int i = 0; i < 25; i++) {
            float w = __ldg(&w2[(co2 * 2 + ci2) * 25 + i]);
            wreg[i] = pack2(w, w);
        }
        bias = __ldg(&b2[co2]);
    }

    stage_pair(sx[0], x, pair0 * 2, t, 256);
    __syncthreads();

    for (int it = 0; it <= NPAIR; it++) {
        if (t < 96) {
            // ---- phase 1: conv1 + relu + pool, pair `it` ----
            if (it < NPAIR) {
                const ull* in = &sx[it & 1][(2 * py1) * 28 + 6 * pxh1];
                ull acc[2][6] = {{0,0,0,0,0,0},{0,0,0,0,0,0}};
#pragma unroll
                for (int iy = 0; iy < 6; iy++) {
                    ull row[10];
#pragma unroll
                    for (int c = 0; c < 10; c += 2) {
                        ulonglong2 v = *(const ulonglong2*)&in[iy * 28 + c];
                        row[c] = v.x; row[c + 1] = v.y;
                    }
#pragma unroll
                    for (int yy = 0; yy < 2; yy++) {
                        const int ky = iy - yy;
                        if (ky >= 0 && ky < 5) {
#pragma unroll
                            for (int cx = 0; cx < 6; cx++)
#pragma unroll
                                for (int kx = 0; kx < 5; kx++)
                                    ffma2(acc[yy][cx], row[cx + kx], wreg[ky * 5 + kx]);
                        }
                    }
                }
                ull* op = &sp1[it & 1][co1 * SP1_CI + py1 * SP1_ROW + pxh1 * 3];
#pragma unroll
                for (int p = 0; p < 3; p++) {
                    float a0,a1,e0,e1,c0,c1,d0,d1;
                    unpk(acc[0][2*p],   a0,a1); unpk(acc[0][2*p+1], e0,e1);
                    unpk(acc[1][2*p],   c0,c1); unpk(acc[1][2*p+1], d0,d1);
                    float vA = fmaxf(fmaxf(fmaxf(a0,e0), fmaxf(c0,d0)) + bias, 0.f);
                    float vB = fmaxf(fmaxf(fmaxf(a1,e1), fmaxf(c1,d1)) + bias, 0.f);
                    op[p] = pack2(vA, vB);
                }
            }
        } else if (t < 128) {
            // ---- stager: pair `it+1` ----
            if (it + 1 < NPAIR)
                stage_pair(sx[(it + 1) & 1], x, (pair0 + it + 1) * 2, t - 96, 32);
        } else {
            // ---- phase 2: conv2 + relu + pool, pair `it-1` ----
            if (it >= 1) {
                const long b0 = (pair0 + it - 1) * 2;
                const ull* in2 = &sp1[(it - 1) & 1][ci2 * SP1_CI + (2 * py2) * SP1_ROW];
                ull acc[2][8];
#pragma unroll
                for (int yy = 0; yy < 2; yy++)
#pragma unroll
                    for (int xx = 0; xx < 8; xx++) acc[yy][xx] = 0ULL;
#pragma unroll
                for (int iy = 0; iy < 6; iy++) {
                    ull row[12];
#pragma unroll
                    for (int c = 0; c < 12; c += 2) {
                        ulonglong2 v = *(const ulonglong2*)&in2[iy * SP1_ROW + c];
                        row[c] = v.x; row[c + 1] = v.y;
                    }
#pragma unroll
                    for (int yy = 0; yy < 2; yy++) {
                        const int ky = iy - yy;
                        if (ky >= 0 && ky < 5) {
#pragma unroll
                            for (int xx = 0; xx < 8; xx++)
#pragma unroll
                                for (int kx = 0; kx < 5; kx++)
                                    ffma2(acc[yy][xx], row[xx + kx], wreg[ky * 5 + kx]);
                        }
                    }
                }
                // reduce over ci (partner lane xor 4)
#pragma unroll
                for (int yy = 0; yy < 2; yy++)
#pragma unroll
                    for (int xx = 0; xx < 8; xx++) {
                        ull o = __shfl_xor_sync(0xffffffffu, acc[yy][xx], 4);
                        acc[yy][xx] = add2(acc[yy][xx], o);
                    }
                if (ci2 == 0) {
                    float4 oA, oB;
                    float* pA = (float*)&oA; float* pB = (float*)&oB;
#pragma unroll
                    for (int p = 0; p < 4; p++) {
                        float a0,a1,e0,e1,c0,c1,d0,d1;
                        unpk(acc[0][2*p],   a0,a1); unpk(acc[0][2*p+1], e0,e1);
                        unpk(acc[1][2*p],   c0,c1); unpk(acc[1][2*p+1], d0,d1);
                        pA[p] = fmaxf(fmaxf(fmaxf(a0,e0), fmaxf(c0,d0)) + bias, 0.f);
                        pB[p] = fmaxf(fmaxf(fmaxf(a1,e1), fmaxf(c1,d1)) + bias, 0.f);
                    }
                    const int off = co2 * 16 + py2 * 4;
                    *(float4*)&g_flat[b0 * 256 + off]       = oA;
                    *(float4*)&g_flat[(b0 + 1) * 256 + off] = oB;
                }
            }
        }
        __syncthreads();
    }
}

// ---------------------------------------------------------------------------
// k_fc: fc1(256->64,relu) + fc2(64->2) + quantum + fc3 + log_softmax
// (unchanged — conflict-free weight LDS.128, 4x8 lane tile)
// ---------------------------------------------------------------------------
__global__ void __launch_bounds__(256, 2) k_fc(const float* __restrict__ fc1w,
                                               const float* __restrict__ fc1b,
                                               const float* __restrict__ fc2w,
                                               const float* __restrict__ fc2b,
                                               const float* __restrict__ fc3w,
                                               const float* __restrict__ fc3b,
                                               const float* __restrict__ qp,
                                               float* __restrict__ out) {
    __shared__ __align__(16) ull s_w[64 * 130];

    const int tid  = threadIdx.x;
    const int warp = tid >> 5, lane = tid & 31;
    const int og = lane & 7, sg = lane >> 3;

    {
        const float2* wsrc = (const float2*)fc1w;
        for (int i = tid; i < 8192; i += 256) {
            float2 v = __ldg(&wsrc[i]);
            const int o = i >> 7, kk = i & 127;
            s_w[(kk >> 1) * 130 + 2 * o + (kk & 1)] = pack2(v.x, v.y);
        }
    }
    __syncthreads();

    const long wg = (long)blockIdx.x * 8 + warp;
    const long b0w = wg * 16;

    const ull* h0 = (const ull*)&g_flat[(b0w + sg * 4) * 256];
    const ull* wbase = &s_w[2 * og];

    ull acc[4][8];
#pragma unroll
    for (int j = 0; j < 4; j++)
#pragma unroll
        for (int oo = 0; oo < 8; oo++) acc[j][oo] = 0ULL;

#pragma unroll 2
    for (int kp = 0; kp < 64; kp++) {
        ull w0[8], w1[8];
#pragma unroll
        for (int oo = 0; oo < 8; oo++) {
            ulonglong2 v = *(const ulonglong2*)&wbase[kp * 130 + 16 * oo];
            w0[oo] = v.x; w1[oo] = v.y;
        }
        ull ha[4], hb[4];
#pragma unroll
        for (int j = 0; j < 4; j++) {
            ulonglong2 hv = __ldg((const ulonglong2*)&h0[j * 128 + 2 * kp]);
            ha[j] = hv.x; hb[j] = hv.y;
        }
#pragma unroll
        for (int j = 0; j < 4; j++)
#pragma unroll
            for (int oo = 0; oo < 8; oo++) {
                ffma2(acc[j][oo], ha[j], w0[oo]);
                ffma2(acc[j][oo], hb[j], w1[oo]);
            }
    }

    float p0[4] = {0,0,0,0}, p1[4] = {0,0,0,0};
#pragma unroll
    for (int oo = 0; oo < 8; oo++) {
        const int o = og + 8 * oo;
        const float bb  = __ldg(&fc1b[o]);
        const float w20 = __ldg(&fc2w[o]);
        const float w21 = __ldg(&fc2w[64 + o]);
#pragma unroll
        for (int j = 0; j < 4; j++) {
            float e, od; unpk(acc[j][oo], e, od);
            float v = fmaxf(e + od + bb, 0.f);
            p0[j] = fmaf(v, w20, p0[j]);
            p1[j] = fmaf(v, w21, p1[j]);
        }
    }
#pragma unroll
    for (int d = 1; d < 8; d <<= 1) {
#pragma unroll
        for (int j = 0; j < 4; j++) {
            p0[j] += __shfl_xor_sync(0xffffffffu, p0[j], d);
            p1[j] += __shfl_xor_sync(0xffffffffu, p1[j], d);
        }
    }
    float x0 = 0.f, x1 = 0.f;
#pragma unroll
    for (int j = 0; j < 4; j++)
        if (og == j) { x0 = p0[j]; x1 = p1[j]; }
    x0 += __ldg(&fc2b[0]);
    x1 += __ldg(&fc2b[1]);
    if (og >= 4) { x0 = 0.f; x1 = 0.f; }

    float cq[8], sq[8];
#pragma unroll
    for (int i = 0; i < 8; i++) {
        float p = __ldg(&qp[i]);
        sincosf(p, &sq[i], &cq[i]);
    }
    const float PI = 3.14159265358979323846f;
    const float ang = (PI - x0) * (PI - x1);
    const float P = x0 + x1, M = x0 - x1;
    float sPp, cPp, sPm, cPm, sMp, cMp, sMm, cMm;
    sincosf(P + ang, &sPp, &cPp);
    sincosf(P - ang, &sPm, &cPm);
    sincosf(M + ang, &sMp, &cMp);
    sincosf(M - ang, &sMm, &cMm);
    float r00 =  0.5f * cPp, i00 = -0.5f * sPp;
    float r01 =  0.5f * cMm, i01 = -0.5f * sMm;
    float r10 =  0.5f * cMp, i10 =  0.5f * sMp;
    float r11 =  0.5f * cPm, i11 =  0.5f * sPm;

#define ROT0(ii) { float c = cq[ii], s = sq[ii], a, bt;                      \
    a = r00; bt = r10; r00 = c*a - s*bt; r10 = s*a + c*bt;                   \
    a = i00; bt = i10; i00 = c*a - s*bt; i10 = s*a + c*bt;                   \
    a = r01; bt = r11; r01 = c*a - s*bt; r11 = s*a + c*bt;                   \
    a = i01; bt = i11; i01 = c*a - s*bt; i11 = s*a + c*bt; }
#define ROT1(ii) { float c = cq[ii], s = sq[ii], a, bt;                      \
    a = r00; bt = r01; r00 = c*a - s*bt; r01 = s*a + c*bt;                   \
    a = i00; bt = i01; i00 = c*a - s*bt; i01 = s*a + c*bt;                   \
    a = r10; bt = r11; r10 = c*a - s*bt; r11 = s*a + c*bt;                   \
    a = i10; bt = i11; i10 = c*a - s*bt; i11 = s*a + c*bt; }
#define CN01 { float tt; tt = r10; r10 = r11; r11 = tt; tt = i10; i10 = i11; i11 = tt; }
#define CN10 { float tt; tt = r01; r01 = r11; r11 = tt; tt = i01; i01 = i11; i11 = tt; }

    ROT0(0); ROT1(1); CN01;
    ROT0(2); ROT1(3); CN10;
    ROT0(4); ROT1(5); CN01;
    ROT0(6); ROT1(7);

    const float q = (r00 * r00 + i00 * i00) - (r01 * r01 + i01 * i01)
                  - (r10 * r10 + i10 * i10) + (r11 * r11 + i11 * i11);

    const float y  = fmaf(q, __ldg(&fc3w[0]), __ldg(&fc3b[0]));
    const float l0 = y, l1 = 1.0f - y;
    const float m  = fmaxf(l0, l1);
    const float lse = m + logf(expf(l0 - m) + expf(l1 - m));

    if (og < 4) {
        float2 res;
        res.x = l0 - lse;
        res.y = l1 - lse;
        ((float2*)out)[b0w + sg * 4 + og] = res;
    }
}

// ---------------------------------------------------------------------------
extern "C" void kernel_launch(void* const* d_in, const int* in_sizes, int n_in,
                              void* d_out, int out_size) {
    const float* x   = (const float*)d_in[0];
    const float* c1w = (const float*)d_in[1];
    const float* c1b = (const float*)d_in[2];
    const float* c2w = (const float*)d_in[3];
    const float* c2b = (const float*)d_in[4];
    const float* f1w = (const float*)d_in[5];
    const float* f1b = (const float*)d_in[6];
    const float* f2w = (const float*)d_in[7];
    const float* f2b = (const float*)d_in[8];
    const float* f3w = (const float*)d_in[9];
    const float* f3b = (const float*)d_in[10];
    const float* qp  = (const float*)d_in[11];
    float* out = (float*)d_out;

    k_conv<<<B_TOTAL / 2 / NPAIR, 256>>>(x, c1w, c1b, c2w, c2b);
    k_fc<<<B_TOTAL / 128, 256>>>(f1w, f1b, f2w, f2b, f3w, f3b, qp, out);
}